// round 15
// baseline (speedup 1.0000x reference)
#include <cuda_runtime.h>
#include <math.h>

#define BB 2
#define PP 8192
#define KK 20
#define NBIN 128
#define ZLO 1.0f
#define ZSPAN 60.0f
#define INVBINW (NBIN / ZSPAN)
#define BINW (ZSPAN / NBIN)
#define DCAP2 9.0f      // 3 m search-radius cap (dropped terms < 4e-7 each)
#define LBUF 24

__device__ double g_acc[2];            // zero at load; self-cleaned by query_kernel
__device__ unsigned g_done;
__device__ int g_hist[8][NBIN];        // zero at load; self-cleaned by scan_kernel
__device__ int g_offs[8][NBIN + 1];
__device__ int g_curs[8][NBIN];
__device__ float4 g_dbp[4][PP];        // z-binned db points (x,y,z, idx bits)
__device__ float4 g_qp[4][PP];         // z-binned transformed queries

// Insert packed key x into 4 sorted chains of 5 (tails at 4,9,14,19).
#define CHAIN_INSERT(keys, x)                                                   \
    do {                                                                        \
        float tt0 = keys[4], tt1 = keys[9], tt2 = keys[14], tt3 = keys[19];     \
        int sel_ = 0; float bv_ = tt0;                                          \
        if (tt1 > bv_) { bv_ = tt1; sel_ = 1; }                                 \
        if (tt2 > bv_) { bv_ = tt2; sel_ = 2; }                                 \
        if (tt3 > bv_) { bv_ = tt3; sel_ = 3; }                                 \
        float x0_ = (sel_ == 0) ? (x) : 3.3e38f;                                \
        float x1_ = (sel_ == 1) ? (x) : 3.3e38f;                                \
        float x2_ = (sel_ == 2) ? (x) : 3.3e38f;                                \
        float x3_ = (sel_ == 3) ? (x) : 3.3e38f;                                \
        _Pragma("unroll")                                                       \
        for (int k_ = 0; k_ < 5; k_++) {                                        \
            float lo_ = fminf(x0_, keys[k_]); x0_ = fmaxf(x0_, keys[k_]); keys[k_] = lo_; } \
        _Pragma("unroll")                                                       \
        for (int k_ = 5; k_ < 10; k_++) {                                       \
            float lo_ = fminf(x1_, keys[k_]); x1_ = fmaxf(x1_, keys[k_]); keys[k_] = lo_; } \
        _Pragma("unroll")                                                       \
        for (int k_ = 10; k_ < 15; k_++) {                                      \
            float lo_ = fminf(x2_, keys[k_]); x2_ = fmaxf(x2_, keys[k_]); keys[k_] = lo_; } \
        _Pragma("unroll")                                                       \
        for (int k_ = 15; k_ < 20; k_++) {                                      \
            float lo_ = fminf(x3_, keys[k_]); x3_ = fmaxf(x3_, keys[k_]); keys[k_] = lo_; } \
    } while (0)

__device__ __forceinline__ int zbin(float z) {
    return min(NBIN - 1, max(0, (int)floorf((z - ZLO) * INVBINW)));
}

__global__ void hist_kernel(const float* __restrict__ xyz1, const float* __restrict__ xyz2,
                            const float* __restrict__ R12, const float* __restrict__ t12,
                            const float* __restrict__ R21, const float* __restrict__ t21,
                            const int* __restrict__ npts1, const int* __restrict__ npts2) {
    const int s = blockIdx.y;
    const int gi = blockIdx.x * blockDim.x + threadIdx.x;
    const int b = gi >> 13;
    const int i = gi & (PP - 1);
    const int set = s * BB + b;
    const float* dbsrc = s ? xyz1 : xyz2;
    const int ldb = (s ? npts1 : npts2)[b];
    if (i < ldb)
        atomicAdd(&g_hist[set * 2][zbin(dbsrc[3 * gi + 2])], 1);
    const float* qsrc = s ? xyz2 : xyz1;
    const int lq = (s ? npts2 : npts1)[b];
    if (i < lq) {
        const float* Rm = (s ? R21 : R12) + b * 9;
        const float* tv = (s ? t21 : t12) + b * 3;
        float ux = qsrc[3 * gi + 0] - tv[0];
        float uy = qsrc[3 * gi + 1] - tv[1];
        float uz = qsrc[3 * gi + 2] - tv[2];
        float qpz = fmaf(Rm[2], ux, fmaf(Rm[5], uy, Rm[8] * uz));
        atomicAdd(&g_hist[set * 2 + 1][zbin(qpz)], 1);
    }
}

// Parallel scan: one block per histogram array; zeroes g_hist after reading.
__global__ void scan_kernel() {
    __shared__ int sv[NBIN];
    const int a = blockIdx.x;
    const int t = threadIdx.x;
    int v = g_hist[a][t];
    g_hist[a][t] = 0;
    sv[t] = v;
    __syncthreads();
    for (int o = 1; o < NBIN; o <<= 1) {
        int x = (t >= o) ? sv[t - o] : 0;
        __syncthreads();
        sv[t] += x;
        __syncthreads();
    }
    g_offs[a][t + 1] = sv[t];
    g_curs[a][t] = sv[t] - v;
    if (t == 0) g_offs[a][0] = 0;
}

__global__ void scatter_kernel(const float* __restrict__ xyz1, const float* __restrict__ xyz2,
                               const float* __restrict__ R12, const float* __restrict__ t12,
                               const float* __restrict__ R21, const float* __restrict__ t21,
                               const int* __restrict__ npts1, const int* __restrict__ npts2) {
    const int s = blockIdx.y;
    const int gi = blockIdx.x * blockDim.x + threadIdx.x;
    const int b = gi >> 13;
    const int i = gi & (PP - 1);
    const int set = s * BB + b;
    const float* dbsrc = s ? xyz1 : xyz2;
    const int ldb = (s ? npts1 : npts2)[b];
    if (i < ldb) {
        float x = dbsrc[3 * gi + 0], y = dbsrc[3 * gi + 1], z = dbsrc[3 * gi + 2];
        int pos = atomicAdd(&g_curs[set * 2][zbin(z)], 1);
        g_dbp[set][pos] = make_float4(x, y, z, __int_as_float(i));
    }
    const float* qsrc = s ? xyz2 : xyz1;
    const int lq = (s ? npts2 : npts1)[b];
    if (i < lq) {
        const float* Rm = (s ? R21 : R12) + b * 9;
        const float* tv = (s ? t21 : t12) + b * 3;
        float ux = qsrc[3 * gi + 0] - tv[0];
        float uy = qsrc[3 * gi + 1] - tv[1];
        float uz = qsrc[3 * gi + 2] - tv[2];
        float qpx = fmaf(Rm[0], ux, fmaf(Rm[3], uy, Rm[6] * uz));
        float qpy = fmaf(Rm[1], ux, fmaf(Rm[4], uy, Rm[7] * uz));
        float qpz = fmaf(Rm[2], ux, fmaf(Rm[5], uy, Rm[8] * uz));
        int pos = atomicAdd(&g_curs[set * 2 + 1][zbin(qpz)], 1);
        g_qp[set][pos] = make_float4(qpx, qpy, qpz, __int_as_float(i));
    }
}

// 8 warps share 32 z-sorted queries; stride-4 monotone bin walks with a SHARED
// per-query threshold (smem min). Chunk-8 distance loop (MLP=8). Sub0 merges
// 7 published shard top-20s; epilogue split across all 8 sub-warps.
__global__ __launch_bounds__(256) void query_kernel(
    const float* __restrict__ xyz1, const float* __restrict__ hsv1,
    const float* __restrict__ normal1, const float* __restrict__ nres1,
    const float* __restrict__ xyz2, const float* __restrict__ hsv2,
    const float* __restrict__ normal2, const float* __restrict__ nres2,
    const float* __restrict__ R12, const float* __restrict__ t12,
    const float* __restrict__ R21, const float* __restrict__ t21,
    const int* __restrict__ npts1, const int* __restrict__ npts2,
    float* __restrict__ out)
{
    const int set = blockIdx.y;
    const int s = set >> 1, b = set & 1;
    const int lane = threadIdx.x & 31;
    const int sub = threadIdx.x >> 5;      // 8 walk shards, one query group
    const int boff = b * PP;

    const float* xq   = s ? xyz2 : xyz1;
    const float* hq   = s ? hsv2 : hsv1;
    const float* nq   = s ? normal2 : normal1;
    const float* rq   = s ? nres2 : nres1;
    const float* xdbr = s ? xyz1 : xyz2;
    const float* ndbr = s ? normal1 : normal2;
    const float* hdb  = s ? hsv1 : hsv2;
    const float* rdb  = s ? nres1 : nres2;
    const float* Rm   = (s ? R21 : R12) + b * 9;
    const int lq = (s ? npts2 : npts1)[b];

    const int base = blockIdx.x * 32;
    const int pos = base + lane;
    const bool act = (base < lq) && (pos < lq);

    float4 qr = (base < lq) ? g_qp[set][act ? pos : base]
                            : make_float4(0.f, 0.f, 0.f, __int_as_float(0));
    const float qpx = qr.x, qpy = qr.y, qpz = qr.z;
    const int iq = __float_as_int(qr.w);

    float keys[KK];
#pragma unroll
    for (int k = 0; k < KK; k++) keys[k] = 3.0e38f;
    float sum = 0.f;

    __shared__ float skeys[7][32][KK + 1];
    __shared__ float smerged[32][KK];
    __shared__ float sthr_sh[32];          // shared per-query threshold (min)

    if (sub == 0) sthr_sh[lane] = act ? DCAP2 : -1.0f;
    __syncthreads();

    if (base < lq) {
        float thr_l = act ? DCAP2 : -1.0f;
        int cnt = 0;
        unsigned lbuf[LBUF];
        volatile float* vshr = &sthr_sh[lane];

        auto compact = [&]() {
            float tail = fmaxf(fmaxf(keys[4], keys[9]), fmaxf(keys[14], keys[19]));
            for (int e = 0; e < cnt; ++e) {
                float xk = __uint_as_float(lbuf[e]);
                if (xk < tail) {
                    CHAIN_INSERT(keys, xk);
                    tail = fmaxf(fmaxf(keys[4], keys[9]), fmaxf(keys[14], keys[19]));
                }
            }
            cnt = 0;
            if (act) {
                float nt = fminf(thr_l, tail * 1.002f);
                float sh = *vshr;                 // other shards' tightenings
                nt = fminf(nt, sh);
                thr_l = nt;
                if (nt < sh) *vshr = nt;          // benign race: monotone min
            }
        };

        const int dbarr = set * 2;
        const float4* __restrict__ dbp = g_dbp[set];

        auto accept = [&](float d2, int j) {
            unsigned key = (__float_as_uint(d2) & 0xFFFFE000u)
                         | (unsigned)__float_as_int(dbp[j].w);
            if (cnt < LBUF) lbuf[cnt++] = key;
            else { float xk = __uint_as_float(key); CHAIN_INSERT(keys, xk); }
        };

        auto procbin = [&](int bin) {
            const int j0 = g_offs[dbarr][bin];
            const int j1 = g_offs[dbarr][bin + 1];
            int j = j0;
            for (; j + 8 <= j1; j += 8) {
                float d2a[8];
#pragma unroll
                for (int u = 0; u < 8; u++) {
                    float4 p = dbp[j + u];
                    float dx = qpx - p.x, dy = qpy - p.y, dz = qpz - p.z;
                    d2a[u] = fmaf(dx, dx, fmaf(dy, dy, dz * dz));
                }
                float m8 = fminf(fminf(fminf(d2a[0], d2a[1]), fminf(d2a[2], d2a[3])),
                                 fminf(fminf(d2a[4], d2a[5]), fminf(d2a[6], d2a[7])));
                if (m8 < thr_l) {
#pragma unroll
                    for (int u = 0; u < 8; u++)
                        if (d2a[u] < thr_l) accept(d2a[u], j + u);
                }
            }
            for (; j < j1; ++j) {
                float4 p = dbp[j];
                float dx = qpx - p.x, dy = qpy - p.y, dz = qpz - p.z;
                float d2 = fmaf(dx, dx, fmaf(dy, dy, dz * dz));
                if (d2 < thr_l) accept(d2, j);
            }
        };

        auto laneneed = [&](int bin) -> bool {
            float loe = ZLO + (float)bin * BINW;
            float hie = loe + BINW;
            float dz = fmaxf(fmaxf(loe - qpz, qpz - hie), 0.f);
            return dz * dz < thr_l;          // false for inactive (thr_l = -1)
        };

        int cb = zbin(qpz);
        int cbm = act ? cb : 0x7fffffff;
        int cbx = act ? cb : (int)0x80000000;
#pragma unroll
        for (int o = 16; o; o >>= 1) {
            cbm = min(cbm, __shfl_xor_sync(0xffffffffu, cbm, o));
            cbx = max(cbx, __shfl_xor_sync(0xffffffffu, cbx, o));
        }
        const int mid = (cbm + cbx) >> 1;

        // Stride-4 monotone walk per sub-warp:
        //   subs 0-3: mid-sub, step -4   subs 4-7: mid+1+(sub-4), step +4
        int bin = (sub < 4) ? (mid - sub) : (mid + 1 + (sub - 4));
        const int step = (sub < 4) ? -4 : 4;
        while (bin >= 0 && bin < NBIN) {
            if (!__ballot_sync(0xffffffffu, laneneed(bin))) break;
            procbin(bin);
            compact();
            bin += step;
        }
        compact();
    }

    // Merge: subs 1-7 publish; sub0 folds (guarded) and broadcasts winners.
    if (sub > 0) {
#pragma unroll
        for (int k = 0; k < KK; k++) skeys[sub - 1][lane][k] = keys[k];
    }
    __syncthreads();
    if (sub == 0) {
        float tail = fmaxf(fmaxf(keys[4], keys[9]), fmaxf(keys[14], keys[19]));
#pragma unroll
        for (int ws = 0; ws < 7; ws++) {
#pragma unroll
            for (int k = 0; k < KK; k++) {
                float x = skeys[ws][lane][k];
                if (x < tail) {
                    CHAIN_INSERT(keys, x);
                    tail = fmaxf(fmaxf(keys[4], keys[9]), fmaxf(keys[14], keys[19]));
                }
            }
        }
#pragma unroll
        for (int k = 0; k < KK; k++) smerged[lane][k] = keys[k];
    }
    __syncthreads();

    // Split epilogue: subs 0-3 take 3 terms (0..11), subs 4-7 take 2 (12..19).
    if (act) {
        const int qi = boff + iq;
        const float qz_own = xq[3 * qi + 2];
        float ell = fmaxf(0.015f * (qz_own - 10.0f), 0.15f);
        float inv_ls = 1.0f / (ell * ell);
        float hx = hq[3 * qi + 0], hy = hq[3 * qi + 1], hz = hq[3 * qi + 2];
        float nxr = nq[3 * qi + 0], nyr = nq[3 * qi + 1], nzr = nq[3 * qi + 2];
        float npx = fmaf(Rm[0], nxr, fmaf(Rm[3], nyr, Rm[6] * nzr));
        float npy = fmaf(Rm[1], nxr, fmaf(Rm[4], nyr, Rm[7] * nzr));
        float npz = fmaf(Rm[2], nxr, fmaf(Rm[5], nyr, Rm[8] * nzr));
        float rqv = rq[qi];
        const int kbeg = (sub < 4) ? (sub * 3) : (12 + (sub - 4) * 2);
        const int kcnt = (sub < 4) ? 3 : 2;
        for (int k2 = 0; k2 < kcnt; k2++) {
            float keyv = smerged[lane][kbeg + k2];
            if (keyv < 1.0e30f) {
                int idx = (int)(__float_as_uint(keyv) & 0x1FFFu);
                int g3 = 3 * (boff + idx);
                float dx = qpx - xdbr[g3 + 0];
                float dy = qpy - xdbr[g3 + 1];
                float dz = qpz - xdbr[g3 + 2];
                float d2 = fmaf(dx, dx, fmaf(dy, dy, dz * dz));
                float ndot = fmaf(npx, ndbr[g3 + 0],
                                  fmaf(npy, ndbr[g3 + 1], npz * ndbr[g3 + 2]));
                float chx = hx - hdb[g3 + 0];
                float chy = hy - hdb[g3 + 1];
                float chz = hz - hdb[g3 + 2];
                float cd = sqrtf(fmaf(chx, chx, fmaf(chy, chy, chz * chz)) + 1e-12f);
                float rk = rdb[boff + idx];
                float alpha = 0.2f / (0.1f + rqv + rk);
                float nk = fmaxf(ndot * alpha, 0.0f);
                sum += __expf(-(d2 * inv_ls + cd * 5.0f)) * nk;
            }
        }
    }

    // Block reduce + single double atomic; last block finalizes + self-cleans.
#pragma unroll
    for (int o = 16; o > 0; o >>= 1) sum += __shfl_down_sync(0xffffffffu, sum, o);
    __shared__ float wsum[8];
    if (lane == 0) wsum[sub] = sum;
    __syncthreads();
    if (threadIdx.x == 0) {
        float bs = 0.f;
#pragma unroll
        for (int w2 = 0; w2 < 8; w2++) bs += wsum[w2];
        atomicAdd(&g_acc[s], (double)bs);
        __threadfence();
        unsigned done = atomicAdd(&g_done, 1u);
        if (done == (unsigned)(gridDim.x * gridDim.y) - 1u) {
            double s1 = (double)npts1[0] + (double)npts1[1];
            double s2 = (double)npts2[0] + (double)npts2[1];
            double k1 = g_acc[0] / (s1 * (double)KK);
            double k2 = g_acc[1] / (s2 * (double)KK);
            out[0] = (float)(0.5 * (k1 + k2));
            g_acc[0] = 0.0;        // self-clean for next replay
            g_acc[1] = 0.0;
            g_done = 0u;
        }
    }
}

extern "C" void kernel_launch(void* const* d_in, const int* in_sizes, int n_in,
                              void* d_out, int out_size) {
    const float* xyz1    = (const float*)d_in[0];
    const float* xyz2    = (const float*)d_in[1];
    const float* hsv1    = (const float*)d_in[2];
    const float* hsv2    = (const float*)d_in[3];
    const float* normal1 = (const float*)d_in[4];
    const float* normal2 = (const float*)d_in[5];
    const float* nres1   = (const float*)d_in[6];
    const float* nres2   = (const float*)d_in[7];
    const float* R12     = (const float*)d_in[8];
    const float* t12     = (const float*)d_in[9];
    const float* R21     = (const float*)d_in[10];
    const float* t21     = (const float*)d_in[11];
    const int*   npts1   = (const int*)d_in[12];
    const int*   npts2   = (const int*)d_in[13];
    float* out = (float*)d_out;

    dim3 bgrid(BB * PP / 256, 2);
    hist_kernel<<<bgrid, 256>>>(xyz1, xyz2, R12, t12, R21, t21, npts1, npts2);
    scan_kernel<<<8, NBIN>>>();
    scatter_kernel<<<bgrid, 256>>>(xyz1, xyz2, R12, t12, R21, t21, npts1, npts2);
    dim3 qgrid(BB * PP / 32, 4);
    query_kernel<<<qgrid, 256>>>(xyz1, hsv1, normal1, nres1,
                                 xyz2, hsv2, normal2, nres2,
                                 R12, t12, R21, t21, npts1, npts2, out);
}

// round 16
// speedup vs baseline: 2.1713x; 2.1713x over previous
#include <cuda_runtime.h>
#include <math.h>

#define BB 2
#define PP 8192
#define KK 20
#define NBIN 128
#define ZLO 1.0f
#define ZSPAN 60.0f
#define INVBINW (NBIN / ZSPAN)
#define BINW (ZSPAN / NBIN)
#define DCAP2 9.0f      // 3 m search-radius cap (dropped terms < 4e-7 each)
#define LBUF 24

__device__ double g_acc[2];            // zero at load; self-cleaned by query_kernel
__device__ unsigned g_done;
__device__ int g_hist[8][NBIN];        // zero at load; self-cleaned by scan_kernel
__device__ int g_offs[8][NBIN + 1];
__device__ int g_curs[8][NBIN];
__device__ float4 g_dbp[4][PP];        // z-binned db points (x,y,z, idx bits)
__device__ float4 g_qp[4][PP];         // z-binned transformed queries

// Insert packed key x into 4 sorted chains of 5 (tails at 4,9,14,19).
#define CHAIN_INSERT(keys, x)                                                   \
    do {                                                                        \
        float tt0 = keys[4], tt1 = keys[9], tt2 = keys[14], tt3 = keys[19];     \
        int sel_ = 0; float bv_ = tt0;                                          \
        if (tt1 > bv_) { bv_ = tt1; sel_ = 1; }                                 \
        if (tt2 > bv_) { bv_ = tt2; sel_ = 2; }                                 \
        if (tt3 > bv_) { bv_ = tt3; sel_ = 3; }                                 \
        float x0_ = (sel_ == 0) ? (x) : 3.3e38f;                                \
        float x1_ = (sel_ == 1) ? (x) : 3.3e38f;                                \
        float x2_ = (sel_ == 2) ? (x) : 3.3e38f;                                \
        float x3_ = (sel_ == 3) ? (x) : 3.3e38f;                                \
        _Pragma("unroll")                                                       \
        for (int k_ = 0; k_ < 5; k_++) {                                        \
            float lo_ = fminf(x0_, keys[k_]); x0_ = fmaxf(x0_, keys[k_]); keys[k_] = lo_; } \
        _Pragma("unroll")                                                       \
        for (int k_ = 5; k_ < 10; k_++) {                                       \
            float lo_ = fminf(x1_, keys[k_]); x1_ = fmaxf(x1_, keys[k_]); keys[k_] = lo_; } \
        _Pragma("unroll")                                                       \
        for (int k_ = 10; k_ < 15; k_++) {                                      \
            float lo_ = fminf(x2_, keys[k_]); x2_ = fmaxf(x2_, keys[k_]); keys[k_] = lo_; } \
        _Pragma("unroll")                                                       \
        for (int k_ = 15; k_ < 20; k_++) {                                      \
            float lo_ = fminf(x3_, keys[k_]); x3_ = fmaxf(x3_, keys[k_]); keys[k_] = lo_; } \
    } while (0)

__device__ __forceinline__ int zbin(float z) {
    return min(NBIN - 1, max(0, (int)floorf((z - ZLO) * INVBINW)));
}

__global__ void hist_kernel(const float* __restrict__ xyz1, const float* __restrict__ xyz2,
                            const float* __restrict__ R12, const float* __restrict__ t12,
                            const float* __restrict__ R21, const float* __restrict__ t21,
                            const int* __restrict__ npts1, const int* __restrict__ npts2) {
    const int s = blockIdx.y;
    const int gi = blockIdx.x * blockDim.x + threadIdx.x;
    const int b = gi >> 13;
    const int i = gi & (PP - 1);
    const int set = s * BB + b;
    const float* dbsrc = s ? xyz1 : xyz2;
    const int ldb = (s ? npts1 : npts2)[b];
    if (i < ldb)
        atomicAdd(&g_hist[set * 2][zbin(dbsrc[3 * gi + 2])], 1);
    const float* qsrc = s ? xyz2 : xyz1;
    const int lq = (s ? npts2 : npts1)[b];
    if (i < lq) {
        const float* Rm = (s ? R21 : R12) + b * 9;
        const float* tv = (s ? t21 : t12) + b * 3;
        float ux = qsrc[3 * gi + 0] - tv[0];
        float uy = qsrc[3 * gi + 1] - tv[1];
        float uz = qsrc[3 * gi + 2] - tv[2];
        float qpz = fmaf(Rm[2], ux, fmaf(Rm[5], uy, Rm[8] * uz));
        atomicAdd(&g_hist[set * 2 + 1][zbin(qpz)], 1);
    }
}

// Parallel scan: one block per histogram array; zeroes g_hist after reading.
__global__ void scan_kernel() {
    __shared__ int sv[NBIN];
    const int a = blockIdx.x;
    const int t = threadIdx.x;
    int v = g_hist[a][t];
    g_hist[a][t] = 0;
    sv[t] = v;
    __syncthreads();
    for (int o = 1; o < NBIN; o <<= 1) {
        int x = (t >= o) ? sv[t - o] : 0;
        __syncthreads();
        sv[t] += x;
        __syncthreads();
    }
    g_offs[a][t + 1] = sv[t];
    g_curs[a][t] = sv[t] - v;
    if (t == 0) g_offs[a][0] = 0;
}

__global__ void scatter_kernel(const float* __restrict__ xyz1, const float* __restrict__ xyz2,
                               const float* __restrict__ R12, const float* __restrict__ t12,
                               const float* __restrict__ R21, const float* __restrict__ t21,
                               const int* __restrict__ npts1, const int* __restrict__ npts2) {
    const int s = blockIdx.y;
    const int gi = blockIdx.x * blockDim.x + threadIdx.x;
    const int b = gi >> 13;
    const int i = gi & (PP - 1);
    const int set = s * BB + b;
    const float* dbsrc = s ? xyz1 : xyz2;
    const int ldb = (s ? npts1 : npts2)[b];
    if (i < ldb) {
        float x = dbsrc[3 * gi + 0], y = dbsrc[3 * gi + 1], z = dbsrc[3 * gi + 2];
        int pos = atomicAdd(&g_curs[set * 2][zbin(z)], 1);
        g_dbp[set][pos] = make_float4(x, y, z, __int_as_float(i));
    }
    const float* qsrc = s ? xyz2 : xyz1;
    const int lq = (s ? npts2 : npts1)[b];
    if (i < lq) {
        const float* Rm = (s ? R21 : R12) + b * 9;
        const float* tv = (s ? t21 : t12) + b * 3;
        float ux = qsrc[3 * gi + 0] - tv[0];
        float uy = qsrc[3 * gi + 1] - tv[1];
        float uz = qsrc[3 * gi + 2] - tv[2];
        float qpx = fmaf(Rm[0], ux, fmaf(Rm[3], uy, Rm[6] * uz));
        float qpy = fmaf(Rm[1], ux, fmaf(Rm[4], uy, Rm[7] * uz));
        float qpz = fmaf(Rm[2], ux, fmaf(Rm[5], uy, Rm[8] * uz));
        int pos = atomicAdd(&g_curs[set * 2 + 1][zbin(qpz)], 1);
        g_qp[set][pos] = make_float4(qpx, qpy, qpz, __int_as_float(i));
    }
}

// 4 warps share 32 z-sorted queries (2 groups/block); stride-2 monotone bin
// walks with SHARED per-query threshold (smem min). Double-buffered chunk-4
// distance loop (prefetch next chunk before testing current). Sub0 merges;
// epilogue split across 4 sub-warps.
__global__ __launch_bounds__(256) void query_kernel(
    const float* __restrict__ xyz1, const float* __restrict__ hsv1,
    const float* __restrict__ normal1, const float* __restrict__ nres1,
    const float* __restrict__ xyz2, const float* __restrict__ hsv2,
    const float* __restrict__ normal2, const float* __restrict__ nres2,
    const float* __restrict__ R12, const float* __restrict__ t12,
    const float* __restrict__ R21, const float* __restrict__ t21,
    const int* __restrict__ npts1, const int* __restrict__ npts2,
    float* __restrict__ out)
{
    const int set = blockIdx.y;
    const int s = set >> 1, b = set & 1;
    const int lane = threadIdx.x & 31;
    const int wid = threadIdx.x >> 5;
    const int wgrp = wid >> 2;             // 2 query groups per block
    const int sub = wid & 3;               // 4 walk shards per group
    const int boff = b * PP;

    const float* xq   = s ? xyz2 : xyz1;
    const float* hq   = s ? hsv2 : hsv1;
    const float* nq   = s ? normal2 : normal1;
    const float* rq   = s ? nres2 : nres1;
    const float* xdbr = s ? xyz1 : xyz2;
    const float* ndbr = s ? normal1 : normal2;
    const float* hdb  = s ? hsv1 : hsv2;
    const float* rdb  = s ? nres1 : nres2;
    const float* Rm   = (s ? R21 : R12) + b * 9;
    const int lq = (s ? npts2 : npts1)[b];

    const int base = (blockIdx.x * 2 + wgrp) * 32;
    const int pos = base + lane;
    const bool act = (base < lq) && (pos < lq);

    float4 qr = (base < lq) ? g_qp[set][act ? pos : base]
                            : make_float4(0.f, 0.f, 0.f, __int_as_float(0));
    const float qpx = qr.x, qpy = qr.y, qpz = qr.z;
    const int iq = __float_as_int(qr.w);

    float keys[KK];
#pragma unroll
    for (int k = 0; k < KK; k++) keys[k] = 3.0e38f;
    float sum = 0.f;

    __shared__ float skeys[2][3][32][KK + 1];
    __shared__ float smerged[2][32][KK];
    __shared__ float sthr_sh[2][32];       // shared per-query threshold (min)

    if (sub == 0) sthr_sh[wgrp][lane] = act ? DCAP2 : -1.0f;
    __syncthreads();

    if (base < lq) {
        float thr_l = act ? DCAP2 : -1.0f;
        int cnt = 0;
        unsigned lbuf[LBUF];
        volatile float* vshr = &sthr_sh[wgrp][lane];

        auto compact = [&]() {
            float tail = fmaxf(fmaxf(keys[4], keys[9]), fmaxf(keys[14], keys[19]));
            for (int e = 0; e < cnt; ++e) {
                float xk = __uint_as_float(lbuf[e]);
                if (xk < tail) {
                    CHAIN_INSERT(keys, xk);
                    tail = fmaxf(fmaxf(keys[4], keys[9]), fmaxf(keys[14], keys[19]));
                }
            }
            cnt = 0;
            if (act) {
                float nt = fminf(thr_l, tail * 1.002f);
                float sh = *vshr;                 // other shards' tightenings
                nt = fminf(nt, sh);
                thr_l = nt;
                if (nt < sh) *vshr = nt;          // benign race: monotone min
            }
        };

        const int dbarr = set * 2;
        const float4* __restrict__ dbp = g_dbp[set];

        auto accept = [&](float d2, int j) {
            unsigned key = (__float_as_uint(d2) & 0xFFFFE000u)
                         | (unsigned)__float_as_int(dbp[j].w);
            if (cnt < LBUF) lbuf[cnt++] = key;
            else { float xk = __uint_as_float(key); CHAIN_INSERT(keys, xk); }
        };

        // Double-buffered chunk-4 scan: next chunk's loads issue before the
        // current chunk's test/accept, hiding LDG latency behind compute.
        auto procbin = [&](int bin) {
            const int j0 = g_offs[dbarr][bin];
            const int j1 = g_offs[dbarr][bin + 1];
            int j = j0;
            if (j + 4 <= j1) {
                float4 c0 = dbp[j], c1 = dbp[j + 1], c2 = dbp[j + 2], c3 = dbp[j + 3];
                for (;;) {
                    const int jn = j + 4;
                    const bool more = (jn + 4 <= j1);
                    float4 n0, n1, n2, n3;
                    if (more) {
                        n0 = dbp[jn]; n1 = dbp[jn + 1]; n2 = dbp[jn + 2]; n3 = dbp[jn + 3];
                    }
                    float dx0 = qpx - c0.x, dy0 = qpy - c0.y, dz0 = qpz - c0.z;
                    float dx1 = qpx - c1.x, dy1 = qpy - c1.y, dz1 = qpz - c1.z;
                    float dx2 = qpx - c2.x, dy2 = qpy - c2.y, dz2 = qpz - c2.z;
                    float dx3 = qpx - c3.x, dy3 = qpy - c3.y, dz3 = qpz - c3.z;
                    float d0 = fmaf(dx0, dx0, fmaf(dy0, dy0, dz0 * dz0));
                    float d1 = fmaf(dx1, dx1, fmaf(dy1, dy1, dz1 * dz1));
                    float d2v = fmaf(dx2, dx2, fmaf(dy2, dy2, dz2 * dz2));
                    float d3 = fmaf(dx3, dx3, fmaf(dy3, dy3, dz3 * dz3));
                    float m4 = fminf(fminf(d0, d1), fminf(d2v, d3));
                    if (m4 < thr_l) {
                        if (d0 < thr_l) accept(d0, j + 0);
                        if (d1 < thr_l) accept(d1, j + 1);
                        if (d2v < thr_l) accept(d2v, j + 2);
                        if (d3 < thr_l) accept(d3, j + 3);
                    }
                    j = jn;
                    if (!more) break;
                    c0 = n0; c1 = n1; c2 = n2; c3 = n3;
                }
            }
            for (; j < j1; ++j) {
                float4 p = dbp[j];
                float dx = qpx - p.x, dy = qpy - p.y, dz = qpz - p.z;
                float d2 = fmaf(dx, dx, fmaf(dy, dy, dz * dz));
                if (d2 < thr_l) accept(d2, j);
            }
        };

        auto laneneed = [&](int bin) -> bool {
            float loe = ZLO + (float)bin * BINW;
            float hie = loe + BINW;
            float dz = fmaxf(fmaxf(loe - qpz, qpz - hie), 0.f);
            return dz * dz < thr_l;          // false for inactive (thr_l = -1)
        };

        int cb = zbin(qpz);
        int cbm = act ? cb : 0x7fffffff;
        int cbx = act ? cb : (int)0x80000000;
#pragma unroll
        for (int o = 16; o; o >>= 1) {
            cbm = min(cbm, __shfl_xor_sync(0xffffffffu, cbm, o));
            cbx = max(cbx, __shfl_xor_sync(0xffffffffu, cbx, o));
        }
        const int mid = (cbm + cbx) >> 1;

        // Stride-2 walk per sub-warp (monotone in z-distance); per-bin compact
        // refreshes thr (own + shared) before the next stop check.
        int bin  = (sub == 0) ? mid     : (sub == 1) ? mid - 1
                 : (sub == 2) ? mid + 1 : mid + 2;
        const int step = (sub < 2) ? -2 : 2;
        while (bin >= 0 && bin < NBIN) {
            if (!__ballot_sync(0xffffffffu, laneneed(bin))) break;
            procbin(bin);
            compact();
            bin += step;
        }
        compact();
    }

    // Merge: subs 1-3 publish; sub0 folds (guarded) and broadcasts winners.
    if (sub > 0) {
#pragma unroll
        for (int k = 0; k < KK; k++) skeys[wgrp][sub - 1][lane][k] = keys[k];
    }
    __syncthreads();
    if (sub == 0) {
        float tail = fmaxf(fmaxf(keys[4], keys[9]), fmaxf(keys[14], keys[19]));
#pragma unroll
        for (int ws = 0; ws < 3; ws++) {
#pragma unroll
            for (int k = 0; k < KK; k++) {
                float x = skeys[wgrp][ws][lane][k];
                if (x < tail) {
                    CHAIN_INSERT(keys, x);
                    tail = fmaxf(fmaxf(keys[4], keys[9]), fmaxf(keys[14], keys[19]));
                }
            }
        }
#pragma unroll
        for (int k = 0; k < KK; k++) smerged[wgrp][lane][k] = keys[k];
    }
    __syncthreads();

    // Split epilogue: each sub-warp computes 5 of the 20 terms.
    if (act) {
        const int qi = boff + iq;
        const float qz_own = xq[3 * qi + 2];
        float ell = fmaxf(0.015f * (qz_own - 10.0f), 0.15f);
        float inv_ls = 1.0f / (ell * ell);
        float hx = hq[3 * qi + 0], hy = hq[3 * qi + 1], hz = hq[3 * qi + 2];
        float nxr = nq[3 * qi + 0], nyr = nq[3 * qi + 1], nzr = nq[3 * qi + 2];
        float npx = fmaf(Rm[0], nxr, fmaf(Rm[3], nyr, Rm[6] * nzr));
        float npy = fmaf(Rm[1], nxr, fmaf(Rm[4], nyr, Rm[7] * nzr));
        float npz = fmaf(Rm[2], nxr, fmaf(Rm[5], nyr, Rm[8] * nzr));
        float rqv = rq[qi];
#pragma unroll
        for (int k2 = 0; k2 < 5; k2++) {
            float keyv = smerged[wgrp][lane][sub * 5 + k2];
            if (keyv < 1.0e30f) {
                int idx = (int)(__float_as_uint(keyv) & 0x1FFFu);
                int g3 = 3 * (boff + idx);
                float dx = qpx - xdbr[g3 + 0];
                float dy = qpy - xdbr[g3 + 1];
                float dz = qpz - xdbr[g3 + 2];
                float d2 = fmaf(dx, dx, fmaf(dy, dy, dz * dz));
                float ndot = fmaf(npx, ndbr[g3 + 0],
                                  fmaf(npy, ndbr[g3 + 1], npz * ndbr[g3 + 2]));
                float chx = hx - hdb[g3 + 0];
                float chy = hy - hdb[g3 + 1];
                float chz = hz - hdb[g3 + 2];
                float cd = sqrtf(fmaf(chx, chx, fmaf(chy, chy, chz * chz)) + 1e-12f);
                float rk = rdb[boff + idx];
                float alpha = 0.2f / (0.1f + rqv + rk);
                float nk = fmaxf(ndot * alpha, 0.0f);
                sum += __expf(-(d2 * inv_ls + cd * 5.0f)) * nk;
            }
        }
    }

    // Block reduce + single double atomic; last block finalizes + self-cleans.
#pragma unroll
    for (int o = 16; o > 0; o >>= 1) sum += __shfl_down_sync(0xffffffffu, sum, o);
    __shared__ float wsum[8];
    if (lane == 0) wsum[wid] = sum;
    __syncthreads();
    if (threadIdx.x == 0) {
        float bs = 0.f;
#pragma unroll
        for (int w2 = 0; w2 < 8; w2++) bs += wsum[w2];
        atomicAdd(&g_acc[s], (double)bs);
        __threadfence();
        unsigned done = atomicAdd(&g_done, 1u);
        if (done == (unsigned)(gridDim.x * gridDim.y) - 1u) {
            double s1 = (double)npts1[0] + (double)npts1[1];
            double s2 = (double)npts2[0] + (double)npts2[1];
            double k1 = g_acc[0] / (s1 * (double)KK);
            double k2 = g_acc[1] / (s2 * (double)KK);
            out[0] = (float)(0.5 * (k1 + k2));
            g_acc[0] = 0.0;        // self-clean for next replay
            g_acc[1] = 0.0;
            g_done = 0u;
        }
    }
}

extern "C" void kernel_launch(void* const* d_in, const int* in_sizes, int n_in,
                              void* d_out, int out_size) {
    const float* xyz1    = (const float*)d_in[0];
    const float* xyz2    = (const float*)d_in[1];
    const float* hsv1    = (const float*)d_in[2];
    const float* hsv2    = (const float*)d_in[3];
    const float* normal1 = (const float*)d_in[4];
    const float* normal2 = (const float*)d_in[5];
    const float* nres1   = (const float*)d_in[6];
    const float* nres2   = (const float*)d_in[7];
    const float* R12     = (const float*)d_in[8];
    const float* t12     = (const float*)d_in[9];
    const float* R21     = (const float*)d_in[10];
    const float* t21     = (const float*)d_in[11];
    const int*   npts1   = (const int*)d_in[12];
    const int*   npts2   = (const int*)d_in[13];
    float* out = (float*)d_out;

    dim3 bgrid(BB * PP / 256, 2);
    hist_kernel<<<bgrid, 256>>>(xyz1, xyz2, R12, t12, R21, t21, npts1, npts2);
    scan_kernel<<<8, NBIN>>>();
    scatter_kernel<<<bgrid, 256>>>(xyz1, xyz2, R12, t12, R21, t21, npts1, npts2);
    dim3 qgrid(PP / 64, 4);   // 128 x-blocks: exactly covers 8192 queries/set (2 groups/block)
    query_kernel<<<qgrid, 256>>>(xyz1, hsv1, normal1, nres1,
                                 xyz2, hsv2, normal2, nres2,
                                 R12, t12, R21, t21, npts1, npts2, out);
}